// round 10
// baseline (speedup 1.0000x reference)
#include <cuda_runtime.h>
#include <cuda_fp16.h>
#include <cstdint>
#include <cstddef>

// ---------------------------------------------------------------------------
// Fused GPTQ 4-bit dequant + fp16 GEMM via mma.sync (HMMA), sm_103 base arch.
//
// R10 vs R9:
//  * exact numerics restored: B smem holds EXACT fp16 integers (q - z - 1)
//    (magic-bias nibbles (1024+q) minus fp16 (1025+z), both exact) -> no
//    fp32 cancellation; epilogue is just rnd16(s * acc). Rowsum pass removed.
//  * loop restructure: THREE stages for A and B, MMA issued FIRST after a
//    single __syncthreads per chunk; producer (dequant B(c+1), q prefetch,
//    cp.async A(c+2)) runs after HMMA issue under the async tensor work.
// CTA 128x128x64, 256 thr, 8 warps (2m x 4n of 64x32), 2 CTAs/SM.
//
//   x      : float32 [4096, 4096]
//   qweight: int32   [512, 11008]  nibble j (shift 4*j) -> k = kp*8 + j
//   qzeros : int32   [1, 1376]     nibble (n%8) -> zero for col n; +1 (GPTQ)
//   scales : float32 [1, 11008]
//   out    : float32 [4096, 11008]
//
// Pre-pass: X f32 -> f16 into g_Xh, K-permuted within each 8-group
// (pairs (t, t+4)) matching ((q >> 4t) & 0x000F000F) | 0x64006400.
// Same permutation on A and B => contraction unchanged.
// ---------------------------------------------------------------------------

static constexpr int M_DIM = 4096;
static constexpr int K_DIM = 4096;
static constexpr int N_DIM = 11008;

static constexpr int BM = 128;
static constexpr int BN = 128;
static constexpr int BK = 64;                    // halves (128 B)
static constexpr int CHUNKS = K_DIM / BK;        // 64

// dynamic smem: A 3x16KB + B 3x16KB = 96 KB (2 CTAs/SM -> 192 KB/SM)
static constexpr uint32_t A_SZ = BM * 128;
static constexpr uint32_t B_SZ = BN * 128;
static constexpr uint32_t SMEM_BYTES = 3 * A_SZ + 3 * B_SZ;  // 98304

__device__ __half g_Xh[(size_t)M_DIM * K_DIM];   // 32 MB scratch (static)

// ---------------- helpers ----------------
__device__ __forceinline__ uint32_t h2u(__half2 h) { return *reinterpret_cast<uint32_t*>(&h); }
__device__ __forceinline__ __half2  u2h(uint32_t u) { return *reinterpret_cast<__half2*>(&u); }
__device__ __forceinline__ float    rnd16(float x) { return __half2float(__float2half_rn(x)); }

__device__ __forceinline__ void cp16(uint32_t dst, const void* src) {
    asm volatile("cp.async.cg.shared.global [%0], [%1], 16;" :: "r"(dst), "l"(src));
}
__device__ __forceinline__ void ldsm4(uint32_t* r, uint32_t addr) {
    asm volatile("ldmatrix.sync.aligned.m8n8.x4.shared.b16 {%0,%1,%2,%3}, [%4];"
                 : "=r"(r[0]), "=r"(r[1]), "=r"(r[2]), "=r"(r[3]) : "r"(addr));
}
__device__ __forceinline__ void mma16816(float* c, const uint32_t* a,
                                         uint32_t b0, uint32_t b1) {
    asm volatile("mma.sync.aligned.m16n8k16.row.col.f32.f16.f16.f32 "
                 "{%0,%1,%2,%3}, {%4,%5,%6,%7}, {%8,%9}, {%0,%1,%2,%3};"
                 : "+f"(c[0]), "+f"(c[1]), "+f"(c[2]), "+f"(c[3])
                 : "r"(a[0]), "r"(a[1]), "r"(a[2]), "r"(a[3]), "r"(b0), "r"(b1));
}

// ---------------------------------------------------------------------------
// Pre-pass: f32 -> f16 with per-8-group K permutation (pairs (t, t+4)).
// ---------------------------------------------------------------------------
__global__ void __launch_bounds__(256)
convert_x(const float* __restrict__ X) {
    const size_t e = (size_t)blockIdx.x * blockDim.x + threadIdx.x;
    if (e >= (size_t)M_DIM * (K_DIM / 8)) return;
    const float4* s = reinterpret_cast<const float4*>(X) + e * 2;
    const float4 lo = s[0];
    const float4 hi = s[1];
    uint4 o;
    o.x = h2u(__floats2half2_rn(lo.x, hi.x));
    o.y = h2u(__floats2half2_rn(lo.y, hi.y));
    o.z = h2u(__floats2half2_rn(lo.z, hi.z));
    o.w = h2u(__floats2half2_rn(lo.w, hi.w));
    reinterpret_cast<uint4*>(g_Xh)[e] = o;
}

// ---------------------------------------------------------------------------
__global__ void __launch_bounds__(256, 2)
gemm_mma(const int*   __restrict__ qweight,
         const int*   __restrict__ qzeros,
         const float* __restrict__ scales,
         float*       __restrict__ Y) {
    extern __shared__ char smem[];
    const uint32_t sb = (uint32_t)__cvta_generic_to_shared(smem);
    const uint32_t aStg[3] = {0u, A_SZ, 2 * A_SZ};
    const uint32_t bStg[3] = {3 * A_SZ, 3 * A_SZ + B_SZ, 3 * A_SZ + 2 * B_SZ};

    const int tid  = threadIdx.x;
    const int warp = tid >> 5;
    const int lane = tid & 31;
    const int wm   = warp >> 2;      // 0..1  (64-row slice)
    const int wn   = warp & 3;       // 0..3  (32-col slice)
    const int bm   = blockIdx.y * BM;
    const int bn   = blockIdx.x * BN;

    // dequant mapping: 2 threads per column, 4 packed rows each
    const int nloc = tid & 127;                  // column 0..127
    const int half = tid >> 7;                   // 0: pr 0-3, 1: pr 4-7
    const int gcol = bn + nloc;
    const int zraw = (qzeros[gcol >> 3] >> ((gcol & 7) * 4)) & 0xF;
    const __half2 z2 = __half2half2(__float2half_rn((float)(1025 + zraw)));
    const int* qcol = qweight + (size_t)half * 4 * N_DIM + gcol;
    const uint32_t bRowOff = (uint32_t)nloc * 128;
    const uint32_t bx = (uint32_t)(nloc & 7) << 4;

    float acc[4][4][4];
#pragma unroll
    for (int i = 0; i < 4; ++i)
#pragma unroll
        for (int j = 0; j < 4; ++j)
#pragma unroll
            for (int t = 0; t < 4; ++t) acc[i][j][t] = 0.0f;

    // A tile loader: chunk c -> stage c%3 (4 x 16B per thread) + commit
    auto loadA = [&](int c) {
        const uint32_t aB = sb + aStg[c % 3];
        const int k0 = c * BK;
#pragma unroll
        for (int i = 0; i < 4; ++i) {
            const int e = tid + i * 256;
            const int r = e >> 3, g = e & 7;
            const uint32_t dst = aB +
                (uint32_t)(r * 128 + ((g * 16) ^ ((r & 7) << 4)));
            cp16(dst, g_Xh + (size_t)(bm + r) * K_DIM + k0 + g * 8);
        }
        asm volatile("cp.async.commit_group;" ::: "memory");
    };

    // dequant 4 packed rows -> EXACT fp16 (q - z - 1) into B stage
    auto dqB = [&](const uint32_t* q, int stg) {
        const uint32_t bB = sb + bStg[stg] + bRowOff;
#pragma unroll
        for (int pr = 0; pr < 4; ++pr) {
            const uint32_t w = q[pr];
            uint32_t u[4];
#pragma unroll
            for (int t = 0; t < 4; ++t) {
                const uint32_t hb = ((w >> (4 * t)) & 0x000F000Fu) | 0x64006400u;
                u[t] = h2u(__hsub2(u2h(hb), z2));
            }
            const uint32_t dst = bB + ((((uint32_t)(half * 4 + pr)) * 16) ^ bx);
            asm volatile("st.shared.v4.b32 [%0], {%1,%2,%3,%4};"
                         :: "r"(dst), "r"(u[0]), "r"(u[1]), "r"(u[2]), "r"(u[3])
                         : "memory");
        }
    };

    // ---- prologue ----
    loadA(0);
    loadA(1);
    {
        uint32_t q0[4];
#pragma unroll
        for (int pr = 0; pr < 4; ++pr)
            q0[pr] = (uint32_t)qcol[(size_t)pr * N_DIM];
        dqB(q0, 0);
    }
    uint32_t qc[4], qn[4];                        // q(1), q(2)
#pragma unroll
    for (int pr = 0; pr < 4; ++pr) {
        qc[pr] = (uint32_t)qcol[(size_t)(8 + pr) * N_DIM];
        qn[pr] = (uint32_t)qcol[(size_t)(16 + pr) * N_DIM];
    }
    asm volatile("cp.async.wait_group 1;" ::: "memory");   // A(0) ready
    __syncthreads();

    for (int c = 0; c < CHUNKS; ++c) {
        const int stg = c % 3;
        const uint32_t aB = sb + aStg[stg];
        const uint32_t bB = sb + bStg[stg];

        // ---- MMA first: fill the tensor queue ----
#pragma unroll
        for (int kk = 0; kk < 4; ++kk) {
            const uint32_t kb = kk * 32;
            uint32_t a[4][4], b[2][4];
#pragma unroll
            for (int j = 0; j < 2; ++j) {
                const int row = wn * 32 + j * 16 + ((lane >> 4) << 3) + (lane & 7);
                const uint32_t addr = bB + row * 128 +
                    ((kb + (((lane >> 3) & 1) << 4)) ^ ((row & 7) << 4));
                ldsm4(b[j], addr);
            }
#pragma unroll
            for (int i = 0; i < 4; ++i) {
                const int row = wm * 64 + i * 16 + (lane & 15);
                const uint32_t addr = aB + row * 128 +
                    ((kb + ((lane >> 4) << 4)) ^ ((row & 7) << 4));
                ldsm4(a[i], addr);
            }
#pragma unroll
            for (int i = 0; i < 4; ++i)
#pragma unroll
                for (int j = 0; j < 2; ++j) {
                    mma16816(acc[i][2 * j],     a[i], b[j][0], b[j][1]);
                    mma16816(acc[i][2 * j + 1], a[i], b[j][2], b[j][3]);
                }
        }

        // ---- producer: B(c+1), q(c+3), A(c+2) ----
        if (c + 1 < CHUNKS) dqB(qc, (c + 1) % 3);
#pragma unroll
        for (int pr = 0; pr < 4; ++pr) qc[pr] = qn[pr];
        if (c + 3 < CHUNKS) {
#pragma unroll
            for (int pr = 0; pr < 4; ++pr)
                qn[pr] = (uint32_t)qcol[(size_t)((c + 3) * 8 + pr) * N_DIM];
        }
        if (c + 2 < CHUNKS) {
            loadA(c + 2);
            asm volatile("cp.async.wait_group 1;" ::: "memory");  // A(c+1) done
        } else {
            asm volatile("cp.async.wait_group 0;" ::: "memory");
        }
        __syncthreads();   // single barrier per chunk
    }

    // ---- epilogue: out = rnd16( s[n] * acc ) ----
#pragma unroll
    for (int i = 0; i < 4; ++i) {
        const int m0 = bm + wm * 64 + i * 16 + (lane >> 2);
        float* y0 = Y + (size_t)m0 * N_DIM;
        float* y1 = y0 + (size_t)8 * N_DIM;
#pragma unroll
        for (int jj = 0; jj < 4; ++jj) {
            const int n0 = bn + wn * 32 + jj * 8 + 2 * (lane & 3);
            const float2 sv = *reinterpret_cast<const float2*>(scales + n0);
            float2 v0, v1;
            v0.x = rnd16(sv.x * acc[i][jj][0]);
            v0.y = rnd16(sv.y * acc[i][jj][1]);
            v1.x = rnd16(sv.x * acc[i][jj][2]);
            v1.y = rnd16(sv.y * acc[i][jj][3]);
            *reinterpret_cast<float2*>(y0 + n0) = v0;
            *reinterpret_cast<float2*>(y1 + n0) = v1;
        }
    }
}

// ---------------------------------------------------------------------------
extern "C" void kernel_launch(void* const* d_in, const int* in_sizes, int n_in,
                              void* d_out, int out_size) {
    const float* x       = (const float*)d_in[0];
    const int*   qweight = (const int*)d_in[1];
    const int*   qzeros  = (const int*)d_in[2];
    const float* scales  = (const float*)d_in[3];
    float*       out     = (float*)d_out;

    cudaFuncSetAttribute(gemm_mma,
                         cudaFuncAttributeMaxDynamicSharedMemorySize, SMEM_BYTES);

    const int groups = M_DIM * (K_DIM / 8);
    convert_x<<<(groups + 255) / 256, 256>>>(x);

    dim3 grid(N_DIM / BN, M_DIM / BM);   // 86 x 32
    gemm_mma<<<grid, 256, SMEM_BYTES>>>(qweight, qzeros, scales, out);
}

// round 11
// speedup vs baseline: 1.1672x; 1.1672x over previous
#include <cuda_runtime.h>
#include <cuda_fp16.h>
#include <cstdint>
#include <cstddef>

// ---------------------------------------------------------------------------
// GPTQ 4-bit: standalone dequant pass + pure streaming fp16 HMMA GEMM.
//
// R11 vs R10/R6: the fused in-loop dequant producer is removed entirely.
//   Pass 1a: convert_x  : X f32 -> f16 (g_Xh), K-permuted pairs (t, t+4)
//   Pass 1b: dequant_w  : W^T [N][K] fp16 (g_Wt), SAME K permutation,
//                         exact reference math fp16(q - z - 1) * s
//   Pass 2 : gemm_mma   : both operands via cp.async, 3-stage, 1 barrier
//                         per chunk, CTA 128x128x64, 8 warps 64x32, 2 CTA/SM.
//
//   x      : float32 [4096, 4096]
//   qweight: int32   [512, 11008]  nibble j (shift 4*j) -> k = kp*8 + j
//   qzeros : int32   [1, 1376]     nibble (n%8) -> zero for col n; +1 (GPTQ)
//   scales : float32 [1, 11008]
//   out    : float32 [4096, 11008]
// ---------------------------------------------------------------------------

static constexpr int M_DIM = 4096;
static constexpr int K_DIM = 4096;
static constexpr int N_DIM = 11008;

static constexpr int BM = 128;
static constexpr int BN = 128;
static constexpr int BK = 64;                    // halves (128 B)
static constexpr int CHUNKS = K_DIM / BK;        // 64
static constexpr int STAGES = 3;

static constexpr uint32_t A_SZ = BM * 128;       // 16 KB
static constexpr uint32_t B_SZ = BN * 128;       // 16 KB
static constexpr uint32_t SMEM_BYTES = STAGES * (A_SZ + B_SZ);  // 96 KB

__device__ __half g_Xh[(size_t)M_DIM * K_DIM];   // 32 MB
__device__ __half g_Wt[(size_t)N_DIM * K_DIM];   // 90 MB, W^T [N][K]

// ---------------- helpers ----------------
__device__ __forceinline__ uint32_t h2u(__half2 h) { return *reinterpret_cast<uint32_t*>(&h); }
__device__ __forceinline__ __half2  u2h(uint32_t u) { return *reinterpret_cast<__half2*>(&u); }
__device__ __forceinline__ float    rnd16(float x) { return __half2float(__float2half_rn(x)); }

__device__ __forceinline__ void cp16(uint32_t dst, const void* src) {
    asm volatile("cp.async.cg.shared.global [%0], [%1], 16;" :: "r"(dst), "l"(src));
}
__device__ __forceinline__ void ldsm4(uint32_t* r, uint32_t addr) {
    asm volatile("ldmatrix.sync.aligned.m8n8.x4.shared.b16 {%0,%1,%2,%3}, [%4];"
                 : "=r"(r[0]), "=r"(r[1]), "=r"(r[2]), "=r"(r[3]) : "r"(addr));
}
__device__ __forceinline__ void mma16816(float* c, const uint32_t* a,
                                         uint32_t b0, uint32_t b1) {
    asm volatile("mma.sync.aligned.m16n8k16.row.col.f32.f16.f16.f32 "
                 "{%0,%1,%2,%3}, {%4,%5,%6,%7}, {%8,%9}, {%0,%1,%2,%3};"
                 : "+f"(c[0]), "+f"(c[1]), "+f"(c[2]), "+f"(c[3])
                 : "r"(a[0]), "r"(a[1]), "r"(a[2]), "r"(a[3]), "r"(b0), "r"(b1));
}

// ---------------------------------------------------------------------------
// Pass 1a: f32 -> f16 with per-8-group K permutation (pairs (t, t+4)).
// ---------------------------------------------------------------------------
__global__ void __launch_bounds__(256)
convert_x(const float* __restrict__ X) {
    const size_t e = (size_t)blockIdx.x * blockDim.x + threadIdx.x;
    if (e >= (size_t)M_DIM * (K_DIM / 8)) return;
    const float4* s = reinterpret_cast<const float4*>(X) + e * 2;
    const float4 lo = s[0];
    const float4 hi = s[1];
    uint4 o;
    o.x = h2u(__floats2half2_rn(lo.x, hi.x));
    o.y = h2u(__floats2half2_rn(lo.y, hi.y));
    o.z = h2u(__floats2half2_rn(lo.z, hi.z));
    o.w = h2u(__floats2half2_rn(lo.w, hi.w));
    reinterpret_cast<uint4*>(g_Xh)[e] = o;
}

// ---------------------------------------------------------------------------
// Pass 1b: dequant W -> W^T [N][K] fp16, same (t, t+4) pair order.
// Thread = (n, kp2) handling packed rows 2*kp2, 2*kp2+1 of column n:
//   q reads coalesced (consecutive n), writes two adjacent 16B = one 32B
//   sector per thread (full-sector efficiency).
// w = fp16( (1024+q) - (1025+z) ) * s   -- all steps exact in fp16.
// ---------------------------------------------------------------------------
__global__ void __launch_bounds__(256)
dequant_w(const int*   __restrict__ qweight,
          const int*   __restrict__ qzeros,
          const float* __restrict__ scales) {
    const size_t idx = (size_t)blockIdx.x * blockDim.x + threadIdx.x;
    if (idx >= (size_t)N_DIM * (K_DIM / 16)) return;
    const int n   = (int)(idx % N_DIM);
    const int kp2 = (int)(idx / N_DIM);          // 0..255
    const int kp  = kp2 * 2;

    const int zraw = (qzeros[n >> 3] >> ((n & 7) * 4)) & 0xF;
    const __half2 z2 = __half2half2(__float2half_rn((float)(1025 + zraw)));
    const __half2 s2 = __half2half2(__float2half_rn(scales[n]));

    __half* dst = g_Wt + (size_t)n * K_DIM + kp * 8;
#pragma unroll
    for (int w2 = 0; w2 < 2; ++w2) {
        const uint32_t w = (uint32_t)qweight[(size_t)(kp + w2) * N_DIM + n];
        uint4 o;
        uint32_t* u = reinterpret_cast<uint32_t*>(&o);
#pragma unroll
        for (int t = 0; t < 4; ++t) {
            const uint32_t hb = ((w >> (4 * t)) & 0x000F000Fu) | 0x64006400u;
            u[t] = h2u(__hmul2(__hsub2(u2h(hb), z2), s2));
        }
        *reinterpret_cast<uint4*>(dst + w2 * 8) = o;
    }
}

// ---------------------------------------------------------------------------
// Pass 2: streaming fp16 GEMM, both operands cp.async, 3 stages.
// Loop order per chunk: wait -> sync -> MMA(c) -> issue(c+2).
// (The sync separates MMA(c-1) reads of stage (c+2)%3 from its rewrite.)
// ---------------------------------------------------------------------------
__global__ void __launch_bounds__(256, 2)
gemm_mma(float* __restrict__ Y) {
    extern __shared__ char smem[];
    const uint32_t sb = (uint32_t)__cvta_generic_to_shared(smem);

    const int tid  = threadIdx.x;
    const int warp = tid >> 5;
    const int lane = tid & 31;
    const int wm   = warp >> 2;      // 0..1  (64-row slice)
    const int wn   = warp & 3;       // 0..3  (32-col slice)
    const int bm   = blockIdx.y * BM;
    const int bn   = blockIdx.x * BN;

    float acc[4][4][4];
#pragma unroll
    for (int i = 0; i < 4; ++i)
#pragma unroll
        for (int j = 0; j < 4; ++j)
#pragma unroll
            for (int t = 0; t < 4; ++t) acc[i][j][t] = 0.0f;

    // per-thread load coords (8 x 16B per thread: 4 for A, 4 for B)
    const int lr = tid >> 3;          // row 0..31 (stepped by 32)
    const int lg = tid & 7;           // 16B group within 128B row
    const uint32_t swOff = (uint32_t)(((lg * 16) ^ ((lr & 7) << 4)));

    auto loadAB = [&](int c) {
        const uint32_t aB = sb + (uint32_t)(c % STAGES) * (A_SZ + B_SZ);
        const uint32_t bB = aB + A_SZ;
        const int k0 = c * BK;
        const __half* aSrc = g_Xh + (size_t)(bm + lr) * K_DIM + k0 + lg * 8;
        const __half* bSrc = g_Wt + (size_t)(bn + lr) * K_DIM + k0 + lg * 8;
#pragma unroll
        for (int i = 0; i < 4; ++i) {
            const uint32_t d = aB + (uint32_t)((lr + i * 32) * 128) + swOff;
            cp16(d, aSrc + (size_t)(i * 32) * K_DIM);
        }
#pragma unroll
        for (int i = 0; i < 4; ++i) {
            const uint32_t d = bB + (uint32_t)((lr + i * 32) * 128) + swOff;
            cp16(d, bSrc + (size_t)(i * 32) * K_DIM);
        }
        asm volatile("cp.async.commit_group;" ::: "memory");
    };

    // ---- prologue: stages 0 and 1 in flight ----
    loadAB(0);
    loadAB(1);

    for (int c = 0; c < CHUNKS; ++c) {
        if (c == CHUNKS - 1) {
            asm volatile("cp.async.wait_group 0;" ::: "memory");
        } else {
            asm volatile("cp.async.wait_group 1;" ::: "memory");
        }
        __syncthreads();   // group(c) visible to all; MMA(c-1) fully retired

        const uint32_t aB = sb + (uint32_t)(c % STAGES) * (A_SZ + B_SZ);
        const uint32_t bB = aB + A_SZ;
#pragma unroll
        for (int kk = 0; kk < 4; ++kk) {
            const uint32_t kb = kk * 32;
            uint32_t a[4][4], b[2][4];
#pragma unroll
            for (int j = 0; j < 2; ++j) {
                const int row = wn * 32 + j * 16 + ((lane >> 4) << 3) + (lane & 7);
                const uint32_t addr = bB + row * 128 +
                    ((kb + (((lane >> 3) & 1) << 4)) ^ ((row & 7) << 4));
                ldsm4(b[j], addr);
            }
#pragma unroll
            for (int i = 0; i < 4; ++i) {
                const int row = wm * 64 + i * 16 + (lane & 15);
                const uint32_t addr = aB + row * 128 +
                    ((kb + ((lane >> 4) << 4)) ^ ((row & 7) << 4));
                ldsm4(a[i], addr);
            }
#pragma unroll
            for (int i = 0; i < 4; ++i)
#pragma unroll
                for (int j = 0; j < 2; ++j) {
                    mma16816(acc[i][2 * j],     a[i], b[j][0], b[j][1]);
                    mma16816(acc[i][2 * j + 1], a[i], b[j][2], b[j][3]);
                }
        }

        if (c + 2 < CHUNKS) loadAB(c + 2);
    }

    // ---- epilogue: out = rnd16(acc)  (scales already in W) ----
#pragma unroll
    for (int i = 0; i < 4; ++i) {
        const int m0 = bm + wm * 64 + i * 16 + (lane >> 2);
        float* y0 = Y + (size_t)m0 * N_DIM;
        float* y1 = y0 + (size_t)8 * N_DIM;
#pragma unroll
        for (int jj = 0; jj < 4; ++jj) {
            const int n0 = bn + wn * 32 + jj * 8 + 2 * (lane & 3);
            float2 v0, v1;
            v0.x = rnd16(acc[i][jj][0]);
            v0.y = rnd16(acc[i][jj][1]);
            v1.x = rnd16(acc[i][jj][2]);
            v1.y = rnd16(acc[i][jj][3]);
            *reinterpret_cast<float2*>(y0 + n0) = v0;
            *reinterpret_cast<float2*>(y1 + n0) = v1;
        }
    }
}

// ---------------------------------------------------------------------------
extern "C" void kernel_launch(void* const* d_in, const int* in_sizes, int n_in,
                              void* d_out, int out_size) {
    const float* x       = (const float*)d_in[0];
    const int*   qweight = (const int*)d_in[1];
    const int*   qzeros  = (const int*)d_in[2];
    const float* scales  = (const float*)d_in[3];
    float*       out     = (float*)d_out;

    cudaFuncSetAttribute(gemm_mma,
                         cudaFuncAttributeMaxDynamicSharedMemorySize, SMEM_BYTES);

    const int xg = M_DIM * (K_DIM / 8);
    convert_x<<<(xg + 255) / 256, 256>>>(x);

    const size_t wg = (size_t)N_DIM * (K_DIM / 16);
    dequant_w<<<(int)((wg + 255) / 256), 256>>>(qweight, qzeros, scales);

    dim3 grid(N_DIM / BN, M_DIM / BM);   // 86 x 32
    gemm_mma<<<grid, 256, SMEM_BYTES>>>(out);
}

// round 12
// speedup vs baseline: 1.2735x; 1.0910x over previous
#include <cuda_runtime.h>
#include <cuda_fp16.h>
#include <cstdint>
#include <cstddef>

// ---------------------------------------------------------------------------
// GPTQ 4-bit: one merged prep pass (X f32->f16 + W dequant) + pure streaming
// fp16 HMMA GEMM, sm_103 base arch.
//
// R12 vs R11:
//  * GEMM warp tile 64x32 -> 64x64 (128-thread CTAs, 4 warps, 2m x 2n);
//    CTA tile 128x128x64, 3 stages, 1 barrier/chunk, 2 CTAs/SM.
//  * convert_x and dequant_w merged into a single kernel (ranges of
//    blockIdx.x) so both memory-bound passes overlap.
//
//   x      : float32 [4096, 4096]
//   qweight: int32   [512, 11008]  nibble j (shift 4*j) -> k = kp*8 + j
//   qzeros : int32   [1, 1376]     nibble (n%8) -> zero for col n; +1 (GPTQ)
//   scales : float32 [1, 11008]
//   out    : float32 [4096, 11008]
//
// K-permutation: both g_Xh and g_Wt store each 8-group of K in pair order
// (t, t+4), matching ((q >> 4t) & 0x000F000F) | 0x64006400. Contraction
// is permutation-invariant.
// Dequant math (exact in fp16): w = ( (1024+q) - (1025+z) ) * s.
// ---------------------------------------------------------------------------

static constexpr int M_DIM = 4096;
static constexpr int K_DIM = 4096;
static constexpr int N_DIM = 11008;

static constexpr int BM = 128;
static constexpr int BN = 128;
static constexpr int BK = 64;                    // halves (128 B)
static constexpr int CHUNKS = K_DIM / BK;        // 64
static constexpr int STAGES = 3;
static constexpr int NTHREADS = 128;             // 4 warps

static constexpr uint32_t A_SZ = BM * 128;       // 16 KB
static constexpr uint32_t B_SZ = BN * 128;       // 16 KB
static constexpr uint32_t SMEM_BYTES = STAGES * (A_SZ + B_SZ);  // 96 KB

__device__ __half g_Xh[(size_t)M_DIM * K_DIM];   // 32 MB
__device__ __half g_Wt[(size_t)N_DIM * K_DIM];   // 90 MB, W^T [N][K]

// ---------------- helpers ----------------
__device__ __forceinline__ uint32_t h2u(__half2 h) { return *reinterpret_cast<uint32_t*>(&h); }
__device__ __forceinline__ __half2  u2h(uint32_t u) { return *reinterpret_cast<__half2*>(&u); }
__device__ __forceinline__ float    rnd16(float x) { return __half2float(__float2half_rn(x)); }

__device__ __forceinline__ void cp16(uint32_t dst, const void* src) {
    asm volatile("cp.async.cg.shared.global [%0], [%1], 16;" :: "r"(dst), "l"(src));
}
__device__ __forceinline__ void ldsm4(uint32_t* r, uint32_t addr) {
    asm volatile("ldmatrix.sync.aligned.m8n8.x4.shared.b16 {%0,%1,%2,%3}, [%4];"
                 : "=r"(r[0]), "=r"(r[1]), "=r"(r[2]), "=r"(r[3]) : "r"(addr));
}
__device__ __forceinline__ void mma16816(float* c, const uint32_t* a,
                                         uint32_t b0, uint32_t b1) {
    asm volatile("mma.sync.aligned.m16n8k16.row.col.f32.f16.f16.f32 "
                 "{%0,%1,%2,%3}, {%4,%5,%6,%7}, {%8,%9}, {%0,%1,%2,%3};"
                 : "+f"(c[0]), "+f"(c[1]), "+f"(c[2]), "+f"(c[3])
                 : "r"(a[0]), "r"(a[1]), "r"(a[2]), "r"(a[3]), "r"(b0), "r"(b1));
}

// ---------------------------------------------------------------------------
// Merged prep: blocks [0, XBLK) convert X; blocks [XBLK, XBLK+WBLK) dequant W.
// ---------------------------------------------------------------------------
static constexpr int XGROUPS = M_DIM * (K_DIM / 8);            // 2M
static constexpr int XBLK    = XGROUPS / 256;                   // 8192
static constexpr long long WGROUPS = (long long)N_DIM * (K_DIM / 16);
static constexpr int WBLK    = (int)((WGROUPS + 255) / 256);    // 11008

__global__ void __launch_bounds__(256)
prep(const float* __restrict__ X,
     const int*   __restrict__ qweight,
     const int*   __restrict__ qzeros,
     const float* __restrict__ scales) {
    if (blockIdx.x < XBLK) {
        // ---- X f32 -> f16, K-permuted pairs (t, t+4) ----
        const size_t e = (size_t)blockIdx.x * 256 + threadIdx.x;
        const float4* s = reinterpret_cast<const float4*>(X) + e * 2;
        const float4 lo = s[0];
        const float4 hi = s[1];
        uint4 o;
        o.x = h2u(__floats2half2_rn(lo.x, hi.x));
        o.y = h2u(__floats2half2_rn(lo.y, hi.y));
        o.z = h2u(__floats2half2_rn(lo.z, hi.z));
        o.w = h2u(__floats2half2_rn(lo.w, hi.w));
        reinterpret_cast<uint4*>(g_Xh)[e] = o;
    } else {
        // ---- W dequant -> W^T [N][K], same pair order ----
        const size_t idx = (size_t)(blockIdx.x - XBLK) * 256 + threadIdx.x;
        if (idx >= (size_t)WGROUPS) return;
        const int n   = (int)(idx % N_DIM);
        const int kp2 = (int)(idx / N_DIM);      // 0..255
        const int kp  = kp2 * 2;

        const int zraw = (qzeros[n >> 3] >> ((n & 7) * 4)) & 0xF;
        const __half2 z2 = __half2half2(__float2half_rn((float)(1025 + zraw)));
        const __half2 s2 = __half2half2(__float2half_rn(scales[n]));

        __half* dst = g_Wt + (size_t)n * K_DIM + kp * 8;
#pragma unroll
        for (int w2 = 0; w2 < 2; ++w2) {
            const uint32_t w = (uint32_t)qweight[(size_t)(kp + w2) * N_DIM + n];
            uint4 o;
            uint32_t* u = reinterpret_cast<uint32_t*>(&o);
#pragma unroll
            for (int t = 0; t < 4; ++t) {
                const uint32_t hb = ((w >> (4 * t)) & 0x000F000Fu) | 0x64006400u;
                u[t] = h2u(__hmul2(__hsub2(u2h(hb), z2), s2));
            }
            *reinterpret_cast<uint4*>(dst + w2 * 8) = o;
        }
    }
}

// ---------------------------------------------------------------------------
// Streaming fp16 GEMM: CTA 128x128x64, 4 warps (2m x 2n of 64x64),
// both operands cp.async, 3 stages, one barrier per chunk, 2 CTAs/SM.
// ---------------------------------------------------------------------------
__global__ void __launch_bounds__(NTHREADS, 2)
gemm_mma(float* __restrict__ Y) {
    extern __shared__ char smem[];
    const uint32_t sb = (uint32_t)__cvta_generic_to_shared(smem);

    const int tid  = threadIdx.x;
    const int warp = tid >> 5;
    const int lane = tid & 31;
    const int wm   = warp >> 1;      // 0..1  (64-row slice)
    const int wn   = warp & 1;       // 0..1  (64-col slice)
    const int bm   = blockIdx.y * BM;
    const int bn   = blockIdx.x * BN;

    float acc[4][8][4];
#pragma unroll
    for (int i = 0; i < 4; ++i)
#pragma unroll
        for (int j = 0; j < 8; ++j)
#pragma unroll
            for (int t = 0; t < 4; ++t) acc[i][j][t] = 0.0f;

    // per-thread load coords: 128 threads, 8 x 16B for A + 8 x 16B for B
    const int lr = tid >> 3;          // row 0..15 (stepped by 16)
    const int lg = tid & 7;           // 16B group within 128B row
    const uint32_t swOff = (uint32_t)(((lg * 16) ^ ((lr & 7) << 4)));

    auto loadAB = [&](int c) {
        const uint32_t aB = sb + (uint32_t)(c % STAGES) * (A_SZ + B_SZ);
        const uint32_t bB = aB + A_SZ;
        const int k0 = c * BK;
        const __half* aSrc = g_Xh + (size_t)(bm + lr) * K_DIM + k0 + lg * 8;
        const __half* bSrc = g_Wt + (size_t)(bn + lr) * K_DIM + k0 + lg * 8;
#pragma unroll
        for (int i = 0; i < 8; ++i) {
            const uint32_t d = aB + (uint32_t)((lr + i * 16) * 128) + swOff;
            cp16(d, aSrc + (size_t)(i * 16) * K_DIM);
        }
#pragma unroll
        for (int i = 0; i < 8; ++i) {
            const uint32_t d = bB + (uint32_t)((lr + i * 16) * 128) + swOff;
            cp16(d, bSrc + (size_t)(i * 16) * K_DIM);
        }
        asm volatile("cp.async.commit_group;" ::: "memory");
    };

    // ---- prologue: stages 0 and 1 in flight ----
    loadAB(0);
    loadAB(1);

    for (int c = 0; c < CHUNKS; ++c) {
        if (c == CHUNKS - 1) {
            asm volatile("cp.async.wait_group 0;" ::: "memory");
        } else {
            asm volatile("cp.async.wait_group 1;" ::: "memory");
        }
        __syncthreads();   // group(c) visible; MMA(c-1) fully retired

        const uint32_t aB = sb + (uint32_t)(c % STAGES) * (A_SZ + B_SZ);
        const uint32_t bB = aB + A_SZ;
#pragma unroll
        for (int kk = 0; kk < 4; ++kk) {
            const uint32_t kb = kk * 32;
            uint32_t a[4][4], b[4][4];
#pragma unroll
            for (int j = 0; j < 4; ++j) {
                const int row = wn * 64 + j * 16 + ((lane >> 4) << 3) + (lane & 7);
                const uint32_t addr = bB + row * 128 +
                    ((kb + (((lane >> 3) & 1) << 4)) ^ ((row & 7) << 4));
                ldsm4(b[j], addr);
            }
#pragma unroll
            for (int i = 0; i < 4; ++i) {
                const int row = wm * 64 + i * 16 + (lane & 15);
                const uint32_t addr = aB + row * 128 +
                    ((kb + ((lane >> 4) << 4)) ^ ((row & 7) << 4));
                ldsm4(a[i], addr);
            }
#pragma unroll
            for (int i = 0; i < 4; ++i)
#pragma unroll
                for (int j = 0; j < 4; ++j) {
                    mma16816(acc[i][2 * j],     a[i], b[j][0], b[j][1]);
                    mma16816(acc[i][2 * j + 1], a[i], b[j][2], b[j][3]);
                }
        }

        if (c + 2 < CHUNKS) loadAB(c + 2);
    }

    // ---- epilogue: out = rnd16(acc)  (scales already folded into W) ----
#pragma unroll
    for (int i = 0; i < 4; ++i) {
        const int m0 = bm + wm * 64 + i * 16 + (lane >> 2);
        float* y0 = Y + (size_t)m0 * N_DIM;
        float* y1 = y0 + (size_t)8 * N_DIM;
#pragma unroll
        for (int jj = 0; jj < 8; ++jj) {
            const int n0 = bn + wn * 64 + jj * 8 + 2 * (lane & 3);
            float2 v0, v1;
            v0.x = rnd16(acc[i][jj][0]);
            v0.y = rnd16(acc[i][jj][1]);
            v1.x = rnd16(acc[i][jj][2]);
            v1.y = rnd16(acc[i][jj][3]);
            *reinterpret_cast<float2*>(y0 + n0) = v0;
            *reinterpret_cast<float2*>(y1 + n0) = v1;
        }
    }
}

// ---------------------------------------------------------------------------
extern "C" void kernel_launch(void* const* d_in, const int* in_sizes, int n_in,
                              void* d_out, int out_size) {
    const float* x       = (const float*)d_in[0];
    const int*   qweight = (const int*)d_in[1];
    const int*   qzeros  = (const int*)d_in[2];
    const float* scales  = (const float*)d_in[3];
    float*       out     = (float*)d_out;

    cudaFuncSetAttribute(gemm_mma,
                         cudaFuncAttributeMaxDynamicSharedMemorySize, SMEM_BYTES);

    prep<<<XBLK + WBLK, 256>>>(x, qweight, qzeros, scales);

    dim3 grid(N_DIM / BN, M_DIM / BM);   // 86 x 32
    gemm_mma<<<grid, NTHREADS, SMEM_BYTES>>>(out);
}